// round 16
// baseline (speedup 1.0000x reference)
#include <cuda_runtime.h>
#include <cuda_fp16.h>
#include <math.h>

// Problem constants
#define Pn   2000
#define Mn   150
#define DGn  2000
#define Fn   256
#define Hn   4
#define N1n  2150   // P + M
#define N2n  4000   // P + DG
#define E1n  137600
#define E2n  256000
#define EGPn 64000
#define EGMn 4800
#define ETOT (E1n + E2n + 2*EGPn + 2*EGMn)   // 531200
#define EHTOT (ETOT/2)                        // 265600 (2 edges/thread)
#define CNT_TOT (N1n + N2n + 2*Pn + 2*Mn)     // 10450
#define NGAT (2*Pn + 2*Mn)                    // 4300 total GAT nodes
#define WHALF (4*Fn*Fn/2)                     // 131072 half2 pairs of gatW

// half-segment boundaries (2 edges per thread)
#define H1  (E1n/2)
#define H2  (H1 + E2n/2)
#define H3  (H2 + EGPn/2)
#define H4  (H3 + EGPn/2)
#define H5  (H4 + EGMn/2)

// Output layout (flattened tuple order)
#define OUT_SIMI 0
#define OUT_DGCN 300000
#define OUT_MED  812000
#define OUT_MGCN 850400
#define OUT_PAT  888800

// PDL: dependent-kernel entry sync (sm_90+)
__device__ __forceinline__ void pdl_wait(){
#if __CUDA_ARCH__ >= 900
    cudaGridDependencySynchronize();
#endif
}

// ---------------- device scratch (static; no allocations) ----------------
// NOTE: invariant — g_cnt / g_wsum / g_colsum are ZERO at kernel_launch entry.
// Zero-initialized at module load; k_final's epilogue re-zeroes them each run.
__device__ __align__(256) __half g_hlat1a[N1n*Fn], g_hlat1b[N1n*Fn];
__device__ __align__(256) __half g_hlat2a[N2n*Fn], g_hlat2b[N2n*Fn];
__device__ float g_acc1[N1n*Fn];
__device__ float g_acc2[N2n*Fn];
__device__ int   g_cnt[CNT_TOT];
__device__ int   g_offs1[N1n+1], g_cur1[N1n+1];
__device__ int   g_offs2[N2n+1], g_cur2[N2n+1];
__device__ __align__(256) int2 g_epack1[E1n];
__device__ __align__(256) int2 g_epack2[E2n];
__device__ int   g_offsg0[Pn+1], g_curg0[Pn+1]; __device__ int g_ssrc0[EGPn];
__device__ int   g_offsg1[Pn+1], g_curg1[Pn+1]; __device__ int g_ssrc1[EGPn];
__device__ int   g_offsg2[Mn+1], g_curg2[Mn+1]; __device__ int g_ssrc2[EGMn];
__device__ int   g_offsg3[Mn+1], g_curg3[Mn+1]; __device__ int g_ssrc3[EGMn];
__device__ __align__(256) __half g_feats[NGAT*Fn];
__device__ __align__(256) __half g_hgatW[4*Fn*Fn];   // half copy of gatW
__device__ float g_el[NGAT*Hn], g_er[NGAT*Hn];
__device__ float g_eall[NGAT*Fn];
__device__ float g_wsum[4];
__device__ float g_colsum[Fn];
__device__ float g_tvec[Mn];

#define GOFF0 0
#define GOFF1 Pn
#define GOFF2 (2*Pn)
#define GOFF3 (2*Pn + Mn)

__device__ __forceinline__ float tanh_fast(float x){
    float t;
    asm("tanh.approx.f32 %0, %1;" : "=f"(t) : "f"(x));
    return t;
}

// ---- fused init (half embeds + half gatW) + histogram (2 edges/thread) ----
__global__ void k_init_hist(const float* __restrict__ pE, const float* __restrict__ mE,
                            const float* __restrict__ dE, const float* __restrict__ gatW,
                            __half* __restrict__ lat1, __half* __restrict__ lat2,
                            __half* __restrict__ hW,
                            const int* __restrict__ a1r, const int* __restrict__ a2r,
                            const int* __restrict__ g0d, const int* __restrict__ g1d,
                            const int* __restrict__ g2d, const int* __restrict__ g3d,
                            int* cnt){
    int i2 = blockIdx.x*blockDim.x + threadIdx.x;   // pairs
    int i = i2*2;
    if (i < N1n*Fn){
        const float2 v = (i < Pn*Fn) ? ((const float2*)pE)[i2]
                                     : ((const float2*)mE)[i2 - Pn*Fn/2];
        ((__half2*)lat1)[i2] = __floats2half2_rn(v.x, v.y);
    } else if (i < (N1n+N2n)*Fn){
        int j2 = i2 - N1n*Fn/2;
        int j = j2*2;
        const float2 v = (j < Pn*Fn) ? ((const float2*)pE)[j2]
                                     : ((const float2*)dE)[j2 - Pn*Fn/2];
        ((__half2*)lat2)[j2] = __floats2half2_rn(v.x, v.y);
    }
    // convert gatW to half (131072 pairs)
    if (i2 < WHALF){
        const float2 wv = ((const float2*)gatW)[i2];
        ((__half2*)hW)[i2] = __floats2half2_rn(wv.x, wv.y);
    }
    // histogram: 2 edges per thread
    int q = i2;
    if (q < EHTOT){
        const int2* src; int base; int qoff;
        if (q < H1){ src = (const int2*)a1r; base = 0; qoff = q; }
        else if (q < H2){ src = (const int2*)a2r; base = N1n; qoff = q - H1; }
        else if (q < H3){ src = (const int2*)g0d; base = N1n+N2n; qoff = q - H2; }
        else if (q < H4){ src = (const int2*)g1d; base = N1n+N2n+Pn; qoff = q - H3; }
        else if (q < H5){ src = (const int2*)g2d; base = N1n+N2n+2*Pn; qoff = q - H4; }
        else { src = (const int2*)g3d; base = N1n+N2n+2*Pn+Mn; qoff = q - H5; }
        int2 k = src[qoff];
        atomicAdd(&cnt[base + k.x], 1);
        atomicAdd(&cnt[base + k.y], 1);
    }
}

// ---- warp-shuffle exclusive scan, n <= 4096, 1024 threads ----
__device__ void exscan_body(const int* __restrict__ cnt, int n, int* offs, int* cur){
    __shared__ int warpsum[32];
    int t = threadIdx.x;
    int lane = t & 31, wid = t >> 5;
    int base = t*4;
    int x0 = (base+0 < n) ? cnt[base+0] : 0;
    int x1 = (base+1 < n) ? cnt[base+1] : 0;
    int x2 = (base+2 < n) ? cnt[base+2] : 0;
    int x3 = (base+3 < n) ? cnt[base+3] : 0;
    int s = x0 + x1 + x2 + x3;
    int scan = s;
    #pragma unroll
    for (int o = 1; o < 32; o <<= 1){
        int y = __shfl_up_sync(0xffffffffu, scan, o);
        if (lane >= o) scan += y;
    }
    if (lane == 31) warpsum[wid] = scan;
    __syncthreads();
    if (wid == 0){
        int ws = warpsum[lane];
        #pragma unroll
        for (int o = 1; o < 32; o <<= 1){
            int y = __shfl_up_sync(0xffffffffu, ws, o);
            if (lane >= o) ws += y;
        }
        warpsum[lane] = ws;
    }
    __syncthreads();
    int excl = scan - s + (wid > 0 ? warpsum[wid-1] : 0);
    int run = excl;
    if (base+0 < n){ offs[base+0] = run; cur[base+0] = run; } run += x0;
    if (base+1 < n){ offs[base+1] = run; cur[base+1] = run; } run += x1;
    if (base+2 < n){ offs[base+2] = run; cur[base+2] = run; } run += x2;
    if (base+3 < n){ offs[base+3] = run; cur[base+3] = run; } run += x3;
    if (t == 1023) offs[n] = warpsum[31];
}
__global__ void k_exscan_all(const int* __restrict__ cnt,
                             int* o1,int* c1,int* o2,int* c2,
                             int* og0,int* cg0,int* og1,int* cg1,
                             int* og2,int* cg2,int* og3,int* cg3){
    pdl_wait();
    switch (blockIdx.x){
        case 0: exscan_body(cnt,                 N1n, o1,  c1);  break;
        case 1: exscan_body(cnt+N1n,             N2n, o2,  c2);  break;
        case 2: exscan_body(cnt+N1n+N2n,         Pn,  og0, cg0); break;
        case 3: exscan_body(cnt+N1n+N2n+Pn,      Pn,  og1, cg1); break;
        case 4: exscan_body(cnt+N1n+N2n+2*Pn,    Mn,  og2, cg2); break;
        case 5: exscan_body(cnt+N1n+N2n+2*Pn+Mn, Mn,  og3, cg3); break;
    }
}

// ---- fused scatter, 2 edges per thread ----
__global__ void k_scatter_all(const int* __restrict__ a1r, const int* __restrict__ a1c, const float* __restrict__ a1v,
                              const int* __restrict__ a2r, const int* __restrict__ a2c, const float* __restrict__ a2v,
                              const int* __restrict__ g0d, const int* __restrict__ g0s,
                              const int* __restrict__ g1d, const int* __restrict__ g1s,
                              const int* __restrict__ g2d, const int* __restrict__ g2s,
                              const int* __restrict__ g3d, const int* __restrict__ g3s,
                              int* cur1, int2* epack1,
                              int* cur2, int2* epack2,
                              int* curg0, int* ssrc0, int* curg1, int* ssrc1,
                              int* curg2, int* ssrc2, int* curg3, int* ssrc3){
    pdl_wait();
    int q = blockIdx.x*blockDim.x + threadIdx.x;
    if (q >= EHTOT) return;
    if (q < H1){
        int2 r = ((const int2*)a1r)[q];
        int2 c = ((const int2*)a1c)[q];
        int2 v = ((const int2*)a1v)[q];
        int p0 = atomicAdd(&cur1[r.x], 1);
        int p1 = atomicAdd(&cur1[r.y], 1);
        epack1[p0] = make_int2(c.x, v.x);
        epack1[p1] = make_int2(c.y, v.y);
    } else if (q < H2){
        int j = q - H1;
        int2 r = ((const int2*)a2r)[j];
        int2 c = ((const int2*)a2c)[j];
        int2 v = ((const int2*)a2v)[j];
        int p0 = atomicAdd(&cur2[r.x], 1);
        int p1 = atomicAdd(&cur2[r.y], 1);
        epack2[p0] = make_int2(c.x, v.x);
        epack2[p1] = make_int2(c.y, v.y);
    } else {
        const int2* dsts; const int2* srcs; int* cur; int* ssrc; int j;
        if (q < H3){ j = q - H2; dsts = (const int2*)g0d; srcs = (const int2*)g0s; cur = curg0; ssrc = ssrc0; }
        else if (q < H4){ j = q - H3; dsts = (const int2*)g1d; srcs = (const int2*)g1s; cur = curg1; ssrc = ssrc1; }
        else if (q < H5){ j = q - H4; dsts = (const int2*)g2d; srcs = (const int2*)g2s; cur = curg2; ssrc = ssrc2; }
        else { j = q - H5; dsts = (const int2*)g3d; srcs = (const int2*)g3s; cur = curg3; ssrc = ssrc3; }
        int2 d = dsts[j];
        int2 s = srcs[j];
        int p0 = atomicAdd(&cur[d.x], 1);
        int p1 = atomicAdd(&cur[d.y], 1);
        ssrc[p0] = s.x; ssrc[p1] = s.y;
    }
}

// ---------------- SpMM: 2 warps per row (128 cols each), uniform edge loads ----------------
__global__ void k_spmm2(const int* __restrict__ offs1, const int2* __restrict__ ep1,
                        const __half* __restrict__ x1, __half* __restrict__ lo1, float* __restrict__ acc1,
                        const int* __restrict__ offs2, const int2* __restrict__ ep2,
                        const __half* __restrict__ x2, __half* __restrict__ lo2, float* __restrict__ acc2,
                        int accumulate, float* outM, float* outD){
    pdl_wait();
    int gw = (blockIdx.x*blockDim.x + threadIdx.x) >> 5;
    int lane = threadIdx.x & 31;
    int row2 = gw >> 1;          // row index across both graphs
    int half = gw & 1;           // which 128-col half of the row
    if (row2 >= N1n + N2n) return;
    const int* offs; const int2* ep; const __half* x;
    __half* lo; float* acc; int w; float* outp = nullptr;
    if (row2 < N1n){
        offs = offs1; ep = ep1; x = x1; lo = lo1; acc = acc1; w = row2;
        if (outM && w >= Pn) outp = outM + (size_t)(w - Pn) * Fn;
    } else {
        offs = offs2; ep = ep2; x = x2; lo = lo2; acc = acc2; w = row2 - N1n;
        if (outD && w >= Pn) outp = outD + (size_t)(w - Pn) * Fn;
    }
    int beg = offs[w], end = offs[w+1];
    int ci = half*32 + lane;     // float2 index within row (4 half cols per lane)
    float a0=0.f,a1=0.f,a2=0.f,a3=0.f;
    // uniform edge loads: all lanes read the same ep[e] (L1 broadcast wavefront)
    int e = beg;
    int nfull = beg + ((end - beg) & ~15);
    for (; e < nfull; e += 16){
        #pragma unroll
        for (int k = 0; k < 16; k++){
            int2 p = __ldg(&ep[e + k]);
            float vv = __int_as_float(p.y);
            float2 raw = ((const float2*)(x + (size_t)p.x * Fn))[ci];
            const __half2* hp = (const __half2*)&raw;
            float2 f0 = __half22float2(hp[0]);
            float2 f1 = __half22float2(hp[1]);
            a0 = fmaf(vv,f0.x,a0); a1 = fmaf(vv,f0.y,a1);
            a2 = fmaf(vv,f1.x,a2); a3 = fmaf(vv,f1.y,a3);
        }
    }
    for (; e < end; e++){
        int2 p = __ldg(&ep[e]);
        float vv = __int_as_float(p.y);
        float2 raw = ((const float2*)(x + (size_t)p.x * Fn))[ci];
        const __half2* hp = (const __half2*)&raw;
        float2 f0 = __half22float2(hp[0]);
        float2 f1 = __half22float2(hp[1]);
        a0 = fmaf(vv,f0.x,a0); a1 = fmaf(vv,f0.y,a1);
        a2 = fmaf(vv,f1.x,a2); a3 = fmaf(vv,f1.y,a3);
    }
    a0 = a0>0.f?a0:0.5f*a0; a1 = a1>0.f?a1:0.5f*a1;
    a2 = a2>0.f?a2:0.5f*a2; a3 = a3>0.f?a3:0.5f*a3;
    float2 o;
    __half2* op = (__half2*)&o;
    op[0] = __floats2half2_rn(a0,a1);
    op[1] = __floats2half2_rn(a2,a3);
    ((float2*)(lo + (size_t)w * Fn))[ci] = o;
    float4* ac = (float4*)(acc + (size_t)w * Fn);
    float4 p0;
    if (accumulate){
        p0 = ac[ci]; p0.x+=a0; p0.y+=a1; p0.z+=a2; p0.w+=a3;
    } else {
        p0 = make_float4(a0,a1,a2,a3);
    }
    ac[ci] = p0;
    if (outp){
        ((float4*)outp)[ci] = p0;
    }
}

// ---------------- batched GEMM (4 GATs), 16-row tiles, half W, fused el/er ----------------
__global__ void k_gemm_elr(const float* __restrict__ acc1, const float* __restrict__ acc2,
                           const __half* __restrict__ hgatW, const float* __restrict__ gatAl,
                           const float* __restrict__ gatAr,
                           __half* __restrict__ feats, float* __restrict__ el, float* __restrict__ er){
    pdl_wait();
    int gi = blockIdx.y;
    const float* A; int n, nodeoff;
    if (gi == 0){ A = acc1;                 n = Pn; nodeoff = GOFF0; }
    else if (gi == 1){ A = acc2;            n = Pn; nodeoff = GOFF1; }
    else if (gi == 2){ A = acc1 + (size_t)Pn*Fn; n = Mn; nodeoff = GOFF2; }
    else { A = acc1 + (size_t)Pn*Fn;        n = Mn; nodeoff = GOFF3; }
    int r0 = blockIdx.x * 16;
    if (r0 >= n) return;
    const __half* W = hgatW + (size_t)gi * Fn * Fn;

    __shared__ float sA[256][16];
    for (int i = threadIdx.x; i < 16*256; i += 256){
        int r = i >> 8, k = i & 255;
        sA[k][r] = (r0 + r < n) ? A[(size_t)(r0+r)*256 + k] : 0.f;
    }
    __syncthreads();
    int c = threadIdx.x;
    float acc[16];
    #pragma unroll
    for (int r = 0; r < 16; r++) acc[r] = 0.f;
    for (int k = 0; k < 256; k++){
        float wv = __half2float(W[k*256 + c]);
        const float4* s4 = (const float4*)sA[k];
        #pragma unroll
        for (int r4 = 0; r4 < 4; r4++){
            float4 av = s4[r4];
            acc[4*r4+0] = fmaf(av.x, wv, acc[4*r4+0]);
            acc[4*r4+1] = fmaf(av.y, wv, acc[4*r4+1]);
            acc[4*r4+2] = fmaf(av.z, wv, acc[4*r4+2]);
            acc[4*r4+3] = fmaf(av.w, wv, acc[4*r4+3]);
        }
    }
    #pragma unroll
    for (int r = 0; r < 16; r++)
        if (r0 + r < n)
            feats[(size_t)(nodeoff + r0 + r)*256 + c] = __float2half_rn(acc[r]);

    float alv = gatAl[gi*256 + c];
    float arv = gatAr[gi*256 + c];
    int lane = c & 31, wid = c >> 5;
    __shared__ float shl[16][8], shr[16][8];
    #pragma unroll
    for (int r = 0; r < 16; r++){
        float vl = acc[r]*alv;
        float vr = acc[r]*arv;
        #pragma unroll
        for (int o = 16; o >= 1; o >>= 1){
            vl += __shfl_xor_sync(0xffffffffu, vl, o);
            vr += __shfl_xor_sync(0xffffffffu, vr, o);
        }
        if (lane == 0){ shl[r][wid] = vl; shr[r][wid] = vr; }
    }
    __syncthreads();
    if (c < 64){
        int r = c >> 2, h = c & 3;
        if (r0 + r < n){
            el[(size_t)(nodeoff + r0 + r)*4 + h] = shl[r][2*h] + shl[r][2*h+1];
            er[(size_t)(nodeoff + r0 + r)*4 + h] = shr[r][2*h] + shr[r][2*h+1];
        }
    }
}

// ---------------- batched GAT: 2 warps per dst node, edge prefetch ----------------
__device__ __forceinline__ float lrelu2(float x){ return x > 0.f ? x : 0.2f*x; }

__global__ void k_gat_all(const int* __restrict__ offsg0, const int* __restrict__ ssrc0,
                          const int* __restrict__ offsg1, const int* __restrict__ ssrc1,
                          const int* __restrict__ offsg2, const int* __restrict__ ssrc2,
                          const int* __restrict__ offsg3, const int* __restrict__ ssrc3,
                          const float* __restrict__ el, const float* __restrict__ er,
                          const __half* __restrict__ feats, const float* __restrict__ gatB,
                          float* __restrict__ eall){
    pdl_wait();
    int gw = (blockIdx.x*blockDim.x + threadIdx.x) >> 5;
    int lane = threadIdx.x & 31;
    int u = gw >> 1;          // node index
    int half = gw & 1;        // which 128-col half (heads 0-1 or 2-3)
    if (u >= NGAT) return;
    const int* offs; const int* ssrc; int w, gi, nodeoff;
    if (u < Pn){ offs = offsg0; ssrc = ssrc0; w = u; gi = 0; nodeoff = GOFF0; }
    else if (u < 2*Pn){ offs = offsg1; ssrc = ssrc1; w = u - Pn; gi = 1; nodeoff = GOFF1; }
    else if (u < 2*Pn + Mn){ offs = offsg2; ssrc = ssrc2; w = u - 2*Pn; gi = 2; nodeoff = GOFF2; }
    else { offs = offsg3; ssrc = ssrc3; w = u - 2*Pn - Mn; gi = 3; nodeoff = GOFF3; }
    int beg = offs[w], end = offs[w+1];
    int ci = half*32 + lane;     // float2 index within row (4 half cols per lane)
    float4 erv4 = *(const float4*)(er + (size_t)u*4);
    float er_a = half ? erv4.z : erv4.x;
    float er_b = half ? erv4.w : erv4.y;

    float ma = -1e30f, mb = -1e30f;
    for (int e = beg + lane; e < end; e += 32){
        int s = ssrc[e];
        float4 elv = *(const float4*)(el + (size_t)(nodeoff + s)*4);
        float el_a = half ? elv.z : elv.x;
        float el_b = half ? elv.w : elv.y;
        ma = fmaxf(ma, lrelu2(el_a + er_a));
        mb = fmaxf(mb, lrelu2(el_b + er_b));
    }
    #pragma unroll
    for (int o = 16; o >= 1; o >>= 1){
        ma = fmaxf(ma, __shfl_xor_sync(0xffffffffu, ma, o));
        mb = fmaxf(mb, __shfl_xor_sync(0xffffffffu, mb, o));
    }

    bool hiHead = (lane >= 16);
    float sa = 0.f, sb = 0.f;
    float a0=0.f,a1=0.f,a2=0.f,a3=0.f;
    // prefetch first edge tile (ssrc + its el row; index 0 is always valid)
    int sp = 0;
    {
        int e0 = beg + lane;
        if (e0 < end) sp = ssrc[e0];
    }
    float4 elp = *(const float4*)(el + (size_t)(nodeoff + sp)*4);
    for (int base = beg; base < end; base += 32){
        int sidx = sp;
        float4 elv = elp;
        bool valid = (base + lane < end);
        // prefetch next tile
        int en = base + 32 + lane;
        if (en < end) sp = ssrc[en];
        elp = *(const float4*)(el + (size_t)(nodeoff + sp)*4);
        float ua = 0.f, ub = 0.f;
        if (valid){
            float el_a = half ? elv.z : elv.x;
            float el_b = half ? elv.w : elv.y;
            ua = __expf(lrelu2(el_a + er_a) - ma);
            ub = __expf(lrelu2(el_b + er_b) - mb);
        } else {
            sidx = 0;
        }
        sa += ua; sb += ub;
        int cnt = min(32, end - base);
        for (int k = 0; k < cnt; k++){
            int ss = __shfl_sync(0xffffffffu, sidx, k);
            float qa = __shfl_sync(0xffffffffu, ua, k);
            float qb = __shfl_sync(0xffffffffu, ub, k);
            float qq = hiHead ? qb : qa;
            float2 raw = ((const float2*)(feats + (size_t)(nodeoff + ss)*Fn))[ci];
            const __half2* hp = (const __half2*)&raw;
            float2 f0 = __half22float2(hp[0]);
            float2 f1 = __half22float2(hp[1]);
            a0 = fmaf(qq,f0.x,a0); a1 = fmaf(qq,f0.y,a1);
            a2 = fmaf(qq,f1.x,a2); a3 = fmaf(qq,f1.y,a3);
        }
    }
    #pragma unroll
    for (int o = 16; o >= 1; o >>= 1){
        sa += __shfl_xor_sync(0xffffffffu, sa, o);
        sb += __shfl_xor_sync(0xffffffffu, sb, o);
    }
    float dd = hiHead ? sb : sa;
    dd = 1.f/(dd + 1e-9f);
    a0 *= dd; a1 *= dd; a2 *= dd; a3 *= dd;

    const float* bias = gatB + gi*256;
    float4 bb = ((const float4*)bias)[ci];
    a0 += bb.x; a1 += bb.y; a2 += bb.z; a3 += bb.w;
    a0 = a0 > 0.f ? a0 : expm1f(a0);
    a1 = a1 > 0.f ? a1 : expm1f(a1);
    a2 = a2 > 0.f ? a2 : expm1f(a2);
    a3 = a3 > 0.f ? a3 : expm1f(a3);
    ((float4*)(eall + (size_t)u * Fn))[ci] = make_float4(a0,a1,a2,a3);
}

// ---------------- semantic attention scores, 16-row tiles ----------------
__global__ void k_semscore(const float* __restrict__ eall,
                           const float* __restrict__ W1, const float* __restrict__ b1,
                           const float* __restrict__ W2, float* wsum){
    pdl_wait();
    int zi = blockIdx.y;
    const float* z = eall + (size_t)((zi==0)?GOFF0:(zi==1)?GOFF1:(zi==2)?GOFF2:GOFF3)*Fn;
    int n = (zi < 2) ? Pn : Mn;
    int r0 = blockIdx.x * 16;
    if (r0 >= n) return;
    __shared__ float sZ[16][256];
    for (int i = threadIdx.x; i < 16*256; i += 128){
        int r = i >> 8, k = i & 255;
        sZ[r][k] = (r0 + r < n) ? z[(size_t)(r0+r)*256 + k] : 0.f;
    }
    __syncthreads();
    int c = threadIdx.x;
    float bc = b1[c];
    float acc[16];
    #pragma unroll
    for (int r = 0; r < 16; r++) acc[r] = bc;
    for (int k = 0; k < 256; k++){
        float w1v = W1[k*128 + c];
        #pragma unroll
        for (int r = 0; r < 16; r++)
            acc[r] = fmaf(sZ[r][k], w1v, acc[r]);
    }
    float w2 = W2[c];
    float local = 0.f;
    #pragma unroll
    for (int r = 0; r < 16; r++)
        if (r0 + r < n) local += tanh_fast(acc[r]) * w2;
    for (int o = 16; o >= 1; o >>= 1)
        local += __shfl_xor_sync(0xffffffffu, local, o);
    __shared__ float red[4];
    if ((threadIdx.x & 31) == 0) red[threadIdx.x >> 5] = local;
    __syncthreads();
    if (threadIdx.x == 0)
        atomicAdd(&wsum[zi], red[0] + red[1] + red[2] + red[3]);
}

// fused combine: patient then med; med part accumulates colsum of relu(med)
__global__ void k_combine2(const float* __restrict__ eall, const float* __restrict__ ws,
                           float* __restrict__ outPat, float* __restrict__ outMed,
                           float* __restrict__ colsum){
    pdl_wait();
    int i = blockIdx.x*blockDim.x + threadIdx.x;
    if (i < Pn*Fn){
        float w0 = ws[0]*(1.f/(float)Pn), w1 = ws[1]*(1.f/(float)Pn);
        float m = fmaxf(w0, w1);
        float x0 = __expf(w0 - m), x1 = __expf(w1 - m);
        float inv = 1.f/(x0 + x1);
        outPat[i] = (x0*inv)*eall[GOFF0*Fn + i] + (x1*inv)*eall[GOFF1*Fn + i];
    } else if (i < Pn*Fn + Mn*Fn){
        int j = i - Pn*Fn;
        float w0 = ws[2]*(1.f/(float)Mn), w1 = ws[3]*(1.f/(float)Mn);
        float m = fmaxf(w0, w1);
        float x0 = __expf(w0 - m), x1 = __expf(w1 - m);
        float inv = 1.f/(x0 + x1);
        float v = (x0*inv)*eall[GOFF2*Fn + j] + (x1*inv)*eall[GOFF3*Fn + j];
        outMed[j] = v;
        atomicAdd(&colsum[j & 255], fmaxf(v, 0.f));
    }
}

// tvec[j] = colsum . W_bot[:,j] -- warp per output, shuffle reduce
__global__ void k_medt(const float* __restrict__ colsum, const float* __restrict__ outW,
                       float* __restrict__ tvec){
    pdl_wait();
    int wpb = blockDim.x >> 5;
    int j = blockIdx.x * wpb + (threadIdx.x >> 5);
    int lane = threadIdx.x & 31;
    if (j >= Mn) return;
    float acc = 0.f;
    #pragma unroll
    for (int kk = 0; kk < 8; kk++){
        int k = kk*32 + lane;
        acc = fmaf(colsum[k], outW[(256 + k)*Mn + j], acc);
    }
    #pragma unroll
    for (int o = 16; o >= 1; o >>= 1)
        acc += __shfl_xor_sync(0xffffffffu, acc, o);
    if (lane == 0) tvec[j] = acc;
}

// simi_pm[p,j] = M*( relu(patient[p]) . W_top[:,j] + b[j] ) + t[j]  -- 8-row tiles
// Epilogue: re-zero cnt/wsum/colsum to restore the entry invariant for the next replay.
__global__ void k_final(const float* __restrict__ patient, const float* __restrict__ outW,
                        const float* __restrict__ outb, const float* __restrict__ tvec,
                        float* __restrict__ simi,
                        int* cnt, float* wsum, float* colsum){
    pdl_wait();
    __shared__ float sA[256][8];
    int r0 = blockIdx.x * 8;
    for (int i = threadIdx.x; i < 8*256; i += blockDim.x){
        int r = i >> 8, k = i & 255;
        float v = (r0 + r < Pn) ? patient[(size_t)(r0+r)*256 + k] : 0.f;
        sA[k][r] = fmaxf(v, 0.f);
    }
    __syncthreads();
    int j = threadIdx.x;
    if (j < Mn){
        float acc[8];
        #pragma unroll
        for (int r = 0; r < 8; r++) acc[r] = 0.f;
        for (int k = 0; k < 256; k++){
            float wv = outW[k*Mn + j];
            const float4 a40 = *(const float4*)&sA[k][0];
            const float4 a41 = *(const float4*)&sA[k][4];
            acc[0] = fmaf(a40.x, wv, acc[0]); acc[1] = fmaf(a40.y, wv, acc[1]);
            acc[2] = fmaf(a40.z, wv, acc[2]); acc[3] = fmaf(a40.w, wv, acc[3]);
            acc[4] = fmaf(a41.x, wv, acc[4]); acc[5] = fmaf(a41.y, wv, acc[5]);
            acc[6] = fmaf(a41.z, wv, acc[6]); acc[7] = fmaf(a41.w, wv, acc[7]);
        }
        float tv = tvec[j], bb = outb[j];
        #pragma unroll
        for (int r = 0; r < 8; r++)
            if (r0 + r < Pn)
                simi[(size_t)(r0+r)*Mn + j] = (float)Mn * (acc[r] + bb) + tv;
    }
    // epilogue: restore zero invariant (grid covers 250*160 = 40000 >= CNT_TOT)
    int g = blockIdx.x * blockDim.x + threadIdx.x;
    if (g < CNT_TOT) cnt[g] = 0;
    if (g < 4) wsum[g] = 0.f;
    if (g < Fn) colsum[g] = 0.f;
}

// ---------------- host launch ----------------
template <typename T>
static T* symaddr(const void* sym){
    void* p = nullptr;
    cudaGetSymbolAddress(&p, sym);
    return (T*)p;
}

// PDL launch helper: dependent kernel may be dispatched while predecessor drains.
template <typename F, typename... Args>
static void pdl_launch(F f, dim3 grid, dim3 block, Args... args){
    cudaLaunchConfig_t cfg = {};
    cfg.gridDim = grid;
    cfg.blockDim = block;
    cudaLaunchAttribute attr[1];
    attr[0].id = cudaLaunchAttributeProgrammaticStreamSerialization;
    attr[0].val.programmaticStreamSerializationAllowed = 1;
    cfg.attrs = attr;
    cfg.numAttrs = 1;
    cudaLaunchKernelEx(&cfg, f, args...);
}

extern "C" void kernel_launch(void* const* d_in, const int* in_sizes, int n_in,
                              void* d_out, int out_size){
    const int*   a1r = (const int*)  d_in[0];
    const int*   a1c = (const int*)  d_in[1];
    const float* a1v = (const float*)d_in[2];
    const int*   a2r = (const int*)  d_in[3];
    const int*   a2c = (const int*)  d_in[4];
    const float* a2v = (const float*)d_in[5];
    const int*   g0s = (const int*)  d_in[6];
    const int*   g0d = (const int*)  d_in[7];
    const int*   g1s = (const int*)  d_in[8];
    const int*   g1d = (const int*)  d_in[9];
    const int*   g2s = (const int*)  d_in[10];
    const int*   g2d = (const int*)  d_in[11];
    const int*   g3s = (const int*)  d_in[12];
    const int*   g3d = (const int*)  d_in[13];
    int kr = (n_in >= 27) ? 1 : 0;
    const float* pE    = (const float*)d_in[14 + kr];
    const float* mE    = (const float*)d_in[15 + kr];
    const float* dE    = (const float*)d_in[16 + kr];
    const float* gatW  = (const float*)d_in[17 + kr];
    const float* gatAl = (const float*)d_in[18 + kr];
    const float* gatAr = (const float*)d_in[19 + kr];
    const float* gatB  = (const float*)d_in[20 + kr];
    const float* saW1  = (const float*)d_in[21 + kr];
    const float* saB1  = (const float*)d_in[22 + kr];
    const float* saW2  = (const float*)d_in[23 + kr];
    const float* outW  = (const float*)d_in[24 + kr];
    const float* outB  = (const float*)d_in[25 + kr];
    float* out = (float*)d_out;

    __half* hlat1a = symaddr<__half>(g_hlat1a); __half* hlat1b = symaddr<__half>(g_hlat1b);
    __half* hlat2a = symaddr<__half>(g_hlat2a); __half* hlat2b = symaddr<__half>(g_hlat2b);
    float* acc1  = symaddr<float>(g_acc1);
    float* acc2  = symaddr<float>(g_acc2);
    int* cnt   = symaddr<int>(g_cnt);
    int* offs1 = symaddr<int>(g_offs1); int* cur1 = symaddr<int>(g_cur1);
    int* offs2 = symaddr<int>(g_offs2); int* cur2 = symaddr<int>(g_cur2);
    int2* epack1 = symaddr<int2>(g_epack1);
    int2* epack2 = symaddr<int2>(g_epack2);
    int* offsg0 = symaddr<int>(g_offsg0); int* curg0 = symaddr<int>(g_curg0); int* ssrc0 = symaddr<int>(g_ssrc0);
    int* offsg1 = symaddr<int>(g_offsg1); int* curg1 = symaddr<int>(g_curg1); int* ssrc1 = symaddr<int>(g_ssrc1);
    int* offsg2 = symaddr<int>(g_offsg2); int* curg2 = symaddr<int>(g_curg2); int* ssrc2 = symaddr<int>(g_ssrc2);
    int* offsg3 = symaddr<int>(g_offsg3); int* curg3 = symaddr<int>(g_curg3); int* ssrc3 = symaddr<int>(g_ssrc3);
    __half* feats = symaddr<__half>(g_feats);
    __half* hgatW = symaddr<__half>(g_hgatW);
    float* el = symaddr<float>(g_el); float* er = symaddr<float>(g_er);
    float* eall = symaddr<float>(g_eall);
    float* wsum = symaddr<float>(g_wsum);
    float* colsum = symaddr<float>(g_colsum);
    float* tvec = symaddr<float>(g_tvec);

    const int B = 256;

    // ---- fused init+hist+W-convert (cnt is zero by invariant) ----
    k_init_hist<<<((N1n+N2n)*Fn/2+B-1)/B, B>>>(pE, mE, dE, gatW, hlat1a, hlat2a, hgatW,
                                               a1r, a2r, g0d, g1d, g2d, g3d, cnt);
    pdl_launch(k_exscan_all, dim3(6), dim3(1024),
               (const int*)cnt, offs1, cur1, offs2, cur2,
               offsg0, curg0, offsg1, curg1, offsg2, curg2, offsg3, curg3);
    pdl_launch(k_scatter_all, dim3((EHTOT+B-1)/B), dim3(B),
               a1r, a1c, a1v, a2r, a2c, a2v,
               g0d, g0s, g1d, g1s, g2d, g2s, g3d, g3s,
               cur1, epack1, cur2, epack2,
               curg0, ssrc0, curg1, ssrc1, curg2, ssrc2, curg3, ssrc3);

    // ---- 2 GNN layers, 2 warps per row ----
    int spmmBlocks = (2*(N1n + N2n) + 7)/8;
    pdl_launch(k_spmm2, dim3(spmmBlocks), dim3(B),
               (const int*)offs1, (const int2*)epack1, (const __half*)hlat1a, hlat1b, acc1,
               (const int*)offs2, (const int2*)epack2, (const __half*)hlat2a, hlat2b, acc2,
               0, (float*)nullptr, (float*)nullptr);
    pdl_launch(k_spmm2, dim3(spmmBlocks), dim3(B),
               (const int*)offs1, (const int2*)epack1, (const __half*)hlat1b, hlat1a, acc1,
               (const int*)offs2, (const int2*)epack2, (const __half*)hlat2b, hlat2a, acc2,
               1, out + OUT_MGCN, out + OUT_DGCN);

    // ---- batched GEMM (half W) + fused el/er (16-row tiles) ----
    pdl_launch(k_gemm_elr, dim3((Pn+15)/16, 4), dim3(256),
               (const float*)acc1, (const float*)acc2, (const __half*)hgatW, gatAl, gatAr,
               feats, el, er);

    // ---- batched GAT aggregate (2 warps per node, prefetch) ----
    pdl_launch(k_gat_all, dim3((2*NGAT+7)/8), dim3(B),
               (const int*)offsg0, (const int*)ssrc0, (const int*)offsg1, (const int*)ssrc1,
               (const int*)offsg2, (const int*)ssrc2, (const int*)offsg3, (const int*)ssrc3,
               (const float*)el, (const float*)er, (const __half*)feats, gatB, eall);

    // ---- semantic attention (16-row tiles) ----
    pdl_launch(k_semscore, dim3((Pn+15)/16, 4), dim3(128),
               (const float*)eall, saW1, saB1, saW2, wsum);
    pdl_launch(k_combine2, dim3(((Pn+Mn)*Fn+B-1)/B), dim3(B),
               (const float*)eall, (const float*)wsum, out + OUT_PAT, out + OUT_MED, colsum);

    // ---- final similarity ----
    pdl_launch(k_medt, dim3((Mn*32+B-1)/B), dim3(B),
               (const float*)colsum, outW, tvec);
    pdl_launch(k_final, dim3((Pn+7)/8), dim3(160),
               (const float*)(out + OUT_PAT), outW, outB, (const float*)tvec,
               out + OUT_SIMI, cnt, wsum, colsum);
}

// round 17
// speedup vs baseline: 1.1118x; 1.1118x over previous
#include <cuda_runtime.h>
#include <cuda_fp16.h>
#include <math.h>

// Problem constants
#define Pn   2000
#define Mn   150
#define DGn  2000
#define Fn   256
#define Hn   4
#define N1n  2150   // P + M
#define N2n  4000   // P + DG
#define E1n  137600
#define E2n  256000
#define EGPn 64000
#define EGMn 4800
#define ETOT (E1n + E2n + 2*EGPn + 2*EGMn)   // 531200
#define EHTOT (ETOT/2)                        // 265600 (2 edges/thread)
#define CNT_TOT (N1n + N2n + 2*Pn + 2*Mn)     // 10450
#define NGAT (2*Pn + 2*Mn)                    // 4300 total GAT nodes
#define WHALF (4*Fn*Fn/2)                     // 131072 half2 pairs of gatW

// half-segment boundaries (2 edges per thread)
#define H1  (E1n/2)
#define H2  (H1 + E2n/2)
#define H3  (H2 + EGPn/2)
#define H4  (H3 + EGPn/2)
#define H5  (H4 + EGMn/2)

// Output layout (flattened tuple order)
#define OUT_SIMI 0
#define OUT_DGCN 300000
#define OUT_MED  812000
#define OUT_MGCN 850400
#define OUT_PAT  888800

// PDL: dependent-kernel entry sync (sm_90+)
__device__ __forceinline__ void pdl_wait(){
#if __CUDA_ARCH__ >= 900
    cudaGridDependencySynchronize();
#endif
}

// ---------------- device scratch (static; no allocations) ----------------
// NOTE: invariant — g_cnt / g_wsum / g_colsum are ZERO at kernel_launch entry.
// Zero-initialized at module load; k_final's epilogue re-zeroes them each run.
__device__ __align__(256) __half g_hlat1a[N1n*Fn], g_hlat1b[N1n*Fn];
__device__ __align__(256) __half g_hlat2a[N2n*Fn], g_hlat2b[N2n*Fn];
__device__ float g_acc1[N1n*Fn];
__device__ float g_acc2[N2n*Fn];
__device__ int   g_cnt[CNT_TOT];
__device__ int   g_offs1[N1n+1], g_cur1[N1n+1];
__device__ int   g_offs2[N2n+1], g_cur2[N2n+1];
__device__ __align__(256) int2 g_epack1[E1n];
__device__ __align__(256) int2 g_epack2[E2n];
__device__ int   g_offsg0[Pn+1], g_curg0[Pn+1]; __device__ int g_ssrc0[EGPn];
__device__ int   g_offsg1[Pn+1], g_curg1[Pn+1]; __device__ int g_ssrc1[EGPn];
__device__ int   g_offsg2[Mn+1], g_curg2[Mn+1]; __device__ int g_ssrc2[EGMn];
__device__ int   g_offsg3[Mn+1], g_curg3[Mn+1]; __device__ int g_ssrc3[EGMn];
__device__ __align__(256) __half g_feats[NGAT*Fn];
__device__ __align__(256) __half g_hgatW[4*Fn*Fn];   // half copy of gatW
__device__ float g_el[NGAT*Hn], g_er[NGAT*Hn];
__device__ float g_eall[NGAT*Fn];
__device__ float g_wsum[4];
__device__ float g_colsum[Fn];
__device__ float g_tvec[Mn];

#define GOFF0 0
#define GOFF1 Pn
#define GOFF2 (2*Pn)
#define GOFF3 (2*Pn + Mn)

__device__ __forceinline__ float tanh_fast(float x){
    float t;
    asm("tanh.approx.f32 %0, %1;" : "=f"(t) : "f"(x));
    return t;
}

// ---- fused init (half embeds + half gatW) + histogram (2 edges/thread) ----
__global__ void k_init_hist(const float* __restrict__ pE, const float* __restrict__ mE,
                            const float* __restrict__ dE, const float* __restrict__ gatW,
                            __half* __restrict__ lat1, __half* __restrict__ lat2,
                            __half* __restrict__ hW,
                            const int* __restrict__ a1r, const int* __restrict__ a2r,
                            const int* __restrict__ g0d, const int* __restrict__ g1d,
                            const int* __restrict__ g2d, const int* __restrict__ g3d,
                            int* cnt){
    int i2 = blockIdx.x*blockDim.x + threadIdx.x;   // pairs
    int i = i2*2;
    if (i < N1n*Fn){
        const float2 v = (i < Pn*Fn) ? ((const float2*)pE)[i2]
                                     : ((const float2*)mE)[i2 - Pn*Fn/2];
        ((__half2*)lat1)[i2] = __floats2half2_rn(v.x, v.y);
    } else if (i < (N1n+N2n)*Fn){
        int j2 = i2 - N1n*Fn/2;
        int j = j2*2;
        const float2 v = (j < Pn*Fn) ? ((const float2*)pE)[j2]
                                     : ((const float2*)dE)[j2 - Pn*Fn/2];
        ((__half2*)lat2)[j2] = __floats2half2_rn(v.x, v.y);
    }
    // convert gatW to half (131072 pairs)
    if (i2 < WHALF){
        const float2 wv = ((const float2*)gatW)[i2];
        ((__half2*)hW)[i2] = __floats2half2_rn(wv.x, wv.y);
    }
    // histogram: 2 edges per thread
    int q = i2;
    if (q < EHTOT){
        const int2* src; int base; int qoff;
        if (q < H1){ src = (const int2*)a1r; base = 0; qoff = q; }
        else if (q < H2){ src = (const int2*)a2r; base = N1n; qoff = q - H1; }
        else if (q < H3){ src = (const int2*)g0d; base = N1n+N2n; qoff = q - H2; }
        else if (q < H4){ src = (const int2*)g1d; base = N1n+N2n+Pn; qoff = q - H3; }
        else if (q < H5){ src = (const int2*)g2d; base = N1n+N2n+2*Pn; qoff = q - H4; }
        else { src = (const int2*)g3d; base = N1n+N2n+2*Pn+Mn; qoff = q - H5; }
        int2 k = src[qoff];
        atomicAdd(&cnt[base + k.x], 1);
        atomicAdd(&cnt[base + k.y], 1);
    }
}

// ---- warp-shuffle exclusive scan, n <= 4096, 1024 threads ----
__device__ void exscan_body(const int* __restrict__ cnt, int n, int* offs, int* cur){
    __shared__ int warpsum[32];
    int t = threadIdx.x;
    int lane = t & 31, wid = t >> 5;
    int base = t*4;
    int x0 = (base+0 < n) ? cnt[base+0] : 0;
    int x1 = (base+1 < n) ? cnt[base+1] : 0;
    int x2 = (base+2 < n) ? cnt[base+2] : 0;
    int x3 = (base+3 < n) ? cnt[base+3] : 0;
    int s = x0 + x1 + x2 + x3;
    int scan = s;
    #pragma unroll
    for (int o = 1; o < 32; o <<= 1){
        int y = __shfl_up_sync(0xffffffffu, scan, o);
        if (lane >= o) scan += y;
    }
    if (lane == 31) warpsum[wid] = scan;
    __syncthreads();
    if (wid == 0){
        int ws = warpsum[lane];
        #pragma unroll
        for (int o = 1; o < 32; o <<= 1){
            int y = __shfl_up_sync(0xffffffffu, ws, o);
            if (lane >= o) ws += y;
        }
        warpsum[lane] = ws;
    }
    __syncthreads();
    int excl = scan - s + (wid > 0 ? warpsum[wid-1] : 0);
    int run = excl;
    if (base+0 < n){ offs[base+0] = run; cur[base+0] = run; } run += x0;
    if (base+1 < n){ offs[base+1] = run; cur[base+1] = run; } run += x1;
    if (base+2 < n){ offs[base+2] = run; cur[base+2] = run; } run += x2;
    if (base+3 < n){ offs[base+3] = run; cur[base+3] = run; } run += x3;
    if (t == 1023) offs[n] = warpsum[31];
}
__global__ void k_exscan_all(const int* __restrict__ cnt,
                             int* o1,int* c1,int* o2,int* c2,
                             int* og0,int* cg0,int* og1,int* cg1,
                             int* og2,int* cg2,int* og3,int* cg3){
    pdl_wait();
    switch (blockIdx.x){
        case 0: exscan_body(cnt,                 N1n, o1,  c1);  break;
        case 1: exscan_body(cnt+N1n,             N2n, o2,  c2);  break;
        case 2: exscan_body(cnt+N1n+N2n,         Pn,  og0, cg0); break;
        case 3: exscan_body(cnt+N1n+N2n+Pn,      Pn,  og1, cg1); break;
        case 4: exscan_body(cnt+N1n+N2n+2*Pn,    Mn,  og2, cg2); break;
        case 5: exscan_body(cnt+N1n+N2n+2*Pn+Mn, Mn,  og3, cg3); break;
    }
}

// ---- fused scatter, 2 edges per thread ----
__global__ void k_scatter_all(const int* __restrict__ a1r, const int* __restrict__ a1c, const float* __restrict__ a1v,
                              const int* __restrict__ a2r, const int* __restrict__ a2c, const float* __restrict__ a2v,
                              const int* __restrict__ g0d, const int* __restrict__ g0s,
                              const int* __restrict__ g1d, const int* __restrict__ g1s,
                              const int* __restrict__ g2d, const int* __restrict__ g2s,
                              const int* __restrict__ g3d, const int* __restrict__ g3s,
                              int* cur1, int2* epack1,
                              int* cur2, int2* epack2,
                              int* curg0, int* ssrc0, int* curg1, int* ssrc1,
                              int* curg2, int* ssrc2, int* curg3, int* ssrc3){
    pdl_wait();
    int q = blockIdx.x*blockDim.x + threadIdx.x;
    if (q >= EHTOT) return;
    if (q < H1){
        int2 r = ((const int2*)a1r)[q];
        int2 c = ((const int2*)a1c)[q];
        int2 v = ((const int2*)a1v)[q];
        int p0 = atomicAdd(&cur1[r.x], 1);
        int p1 = atomicAdd(&cur1[r.y], 1);
        epack1[p0] = make_int2(c.x, v.x);
        epack1[p1] = make_int2(c.y, v.y);
    } else if (q < H2){
        int j = q - H1;
        int2 r = ((const int2*)a2r)[j];
        int2 c = ((const int2*)a2c)[j];
        int2 v = ((const int2*)a2v)[j];
        int p0 = atomicAdd(&cur2[r.x], 1);
        int p1 = atomicAdd(&cur2[r.y], 1);
        epack2[p0] = make_int2(c.x, v.x);
        epack2[p1] = make_int2(c.y, v.y);
    } else {
        const int2* dsts; const int2* srcs; int* cur; int* ssrc; int j;
        if (q < H3){ j = q - H2; dsts = (const int2*)g0d; srcs = (const int2*)g0s; cur = curg0; ssrc = ssrc0; }
        else if (q < H4){ j = q - H3; dsts = (const int2*)g1d; srcs = (const int2*)g1s; cur = curg1; ssrc = ssrc1; }
        else if (q < H5){ j = q - H4; dsts = (const int2*)g2d; srcs = (const int2*)g2s; cur = curg2; ssrc = ssrc2; }
        else { j = q - H5; dsts = (const int2*)g3d; srcs = (const int2*)g3s; cur = curg3; ssrc = ssrc3; }
        int2 d = dsts[j];
        int2 s = srcs[j];
        int p0 = atomicAdd(&cur[d.x], 1);
        int p1 = atomicAdd(&cur[d.y], 1);
        ssrc[p0] = s.x; ssrc[p1] = s.y;
    }
}

// ---------------- SpMM: 2 warps per row (128 cols each), shfl staging + prefetch ----------------
__global__ void k_spmm2(const int* __restrict__ offs1, const int2* __restrict__ ep1,
                        const __half* __restrict__ x1, __half* __restrict__ lo1, float* __restrict__ acc1,
                        const int* __restrict__ offs2, const int2* __restrict__ ep2,
                        const __half* __restrict__ x2, __half* __restrict__ lo2, float* __restrict__ acc2,
                        int accumulate, float* outM, float* outD){
    pdl_wait();
    int gw = (blockIdx.x*blockDim.x + threadIdx.x) >> 5;
    int lane = threadIdx.x & 31;
    int row2 = gw >> 1;          // row index across both graphs
    int half = gw & 1;           // which 128-col half of the row
    if (row2 >= N1n + N2n) return;
    const int* offs; const int2* ep; const __half* x;
    __half* lo; float* acc; int w; float* outp = nullptr;
    if (row2 < N1n){
        offs = offs1; ep = ep1; x = x1; lo = lo1; acc = acc1; w = row2;
        if (outM && w >= Pn) outp = outM + (size_t)(w - Pn) * Fn;
    } else {
        offs = offs2; ep = ep2; x = x2; lo = lo2; acc = acc2; w = row2 - N1n;
        if (outD && w >= Pn) outp = outD + (size_t)(w - Pn) * Fn;
    }
    int beg = offs[w], end = offs[w+1];
    int ci = half*32 + lane;     // float2 index within row (4 half cols per lane)
    float a0=0.f,a1=0.f,a2=0.f,a3=0.f;
    // prefetch first edge tile
    int2 p = make_int2(0, 0);
    {
        int e0 = beg + lane;
        if (e0 < end) p = ep[e0];
    }
    for (int base = beg; base < end; base += 32){
        int c, cnt = min(32, end - base);
        float v;
        if (base + lane < end){ c = p.x; v = __int_as_float(p.y); }
        else { c = 0; v = 0.f; }
        // prefetch next tile while computing this one
        int en = base + 32 + lane;
        if (en < end) p = ep[en];
        if (cnt == 32){
            #pragma unroll 16
            for (int k = 0; k < 32; k++){
                int cc = __shfl_sync(0xffffffffu, c, k);
                float vv = __shfl_sync(0xffffffffu, v, k);
                float2 raw = ((const float2*)(x + (size_t)cc * Fn))[ci];
                const __half2* hp = (const __half2*)&raw;
                float2 f0 = __half22float2(hp[0]);
                float2 f1 = __half22float2(hp[1]);
                a0 = fmaf(vv,f0.x,a0); a1 = fmaf(vv,f0.y,a1);
                a2 = fmaf(vv,f1.x,a2); a3 = fmaf(vv,f1.y,a3);
            }
        } else {
            for (int k = 0; k < cnt; k++){
                int cc = __shfl_sync(0xffffffffu, c, k);
                float vv = __shfl_sync(0xffffffffu, v, k);
                float2 raw = ((const float2*)(x + (size_t)cc * Fn))[ci];
                const __half2* hp = (const __half2*)&raw;
                float2 f0 = __half22float2(hp[0]);
                float2 f1 = __half22float2(hp[1]);
                a0 = fmaf(vv,f0.x,a0); a1 = fmaf(vv,f0.y,a1);
                a2 = fmaf(vv,f1.x,a2); a3 = fmaf(vv,f1.y,a3);
            }
        }
    }
    a0 = a0>0.f?a0:0.5f*a0; a1 = a1>0.f?a1:0.5f*a1;
    a2 = a2>0.f?a2:0.5f*a2; a3 = a3>0.f?a3:0.5f*a3;
    // lat store is dead in layer 2 (nothing reads it after the final SpMM)
    if (!accumulate){
        float2 o;
        __half2* op = (__half2*)&o;
        op[0] = __floats2half2_rn(a0,a1);
        op[1] = __floats2half2_rn(a2,a3);
        ((float2*)(lo + (size_t)w * Fn))[ci] = o;
    }
    float4* ac = (float4*)(acc + (size_t)w * Fn);
    float4 p0;
    if (accumulate){
        p0 = ac[ci]; p0.x+=a0; p0.y+=a1; p0.z+=a2; p0.w+=a3;
    } else {
        p0 = make_float4(a0,a1,a2,a3);
    }
    ac[ci] = p0;
    if (outp){
        ((float4*)outp)[ci] = p0;
    }
}

// ---------------- batched GEMM (4 GATs), 16-row tiles, half W, fused el/er ----------------
__global__ void k_gemm_elr(const float* __restrict__ acc1, const float* __restrict__ acc2,
                           const __half* __restrict__ hgatW, const float* __restrict__ gatAl,
                           const float* __restrict__ gatAr,
                           __half* __restrict__ feats, float* __restrict__ el, float* __restrict__ er){
    pdl_wait();
    int gi = blockIdx.y;
    const float* A; int n, nodeoff;
    if (gi == 0){ A = acc1;                 n = Pn; nodeoff = GOFF0; }
    else if (gi == 1){ A = acc2;            n = Pn; nodeoff = GOFF1; }
    else if (gi == 2){ A = acc1 + (size_t)Pn*Fn; n = Mn; nodeoff = GOFF2; }
    else { A = acc1 + (size_t)Pn*Fn;        n = Mn; nodeoff = GOFF3; }
    int r0 = blockIdx.x * 16;
    if (r0 >= n) return;
    const __half* W = hgatW + (size_t)gi * Fn * Fn;

    __shared__ float sA[256][16];
    for (int i = threadIdx.x; i < 16*256; i += 256){
        int r = i >> 8, k = i & 255;
        sA[k][r] = (r0 + r < n) ? A[(size_t)(r0+r)*256 + k] : 0.f;
    }
    __syncthreads();
    int c = threadIdx.x;
    float acc[16];
    #pragma unroll
    for (int r = 0; r < 16; r++) acc[r] = 0.f;
    for (int k = 0; k < 256; k++){
        float wv = __half2float(W[k*256 + c]);
        const float4* s4 = (const float4*)sA[k];
        #pragma unroll
        for (int r4 = 0; r4 < 4; r4++){
            float4 av = s4[r4];
            acc[4*r4+0] = fmaf(av.x, wv, acc[4*r4+0]);
            acc[4*r4+1] = fmaf(av.y, wv, acc[4*r4+1]);
            acc[4*r4+2] = fmaf(av.z, wv, acc[4*r4+2]);
            acc[4*r4+3] = fmaf(av.w, wv, acc[4*r4+3]);
        }
    }
    #pragma unroll
    for (int r = 0; r < 16; r++)
        if (r0 + r < n)
            feats[(size_t)(nodeoff + r0 + r)*256 + c] = __float2half_rn(acc[r]);

    float alv = gatAl[gi*256 + c];
    float arv = gatAr[gi*256 + c];
    int lane = c & 31, wid = c >> 5;
    __shared__ float shl[16][8], shr[16][8];
    #pragma unroll
    for (int r = 0; r < 16; r++){
        float vl = acc[r]*alv;
        float vr = acc[r]*arv;
        #pragma unroll
        for (int o = 16; o >= 1; o >>= 1){
            vl += __shfl_xor_sync(0xffffffffu, vl, o);
            vr += __shfl_xor_sync(0xffffffffu, vr, o);
        }
        if (lane == 0){ shl[r][wid] = vl; shr[r][wid] = vr; }
    }
    __syncthreads();
    if (c < 64){
        int r = c >> 2, h = c & 3;
        if (r0 + r < n){
            el[(size_t)(nodeoff + r0 + r)*4 + h] = shl[r][2*h] + shl[r][2*h+1];
            er[(size_t)(nodeoff + r0 + r)*4 + h] = shr[r][2*h] + shr[r][2*h+1];
        }
    }
}

// ---------------- batched GAT: 2 warps per dst node, edge prefetch ----------------
__device__ __forceinline__ float lrelu2(float x){ return x > 0.f ? x : 0.2f*x; }

__global__ void k_gat_all(const int* __restrict__ offsg0, const int* __restrict__ ssrc0,
                          const int* __restrict__ offsg1, const int* __restrict__ ssrc1,
                          const int* __restrict__ offsg2, const int* __restrict__ ssrc2,
                          const int* __restrict__ offsg3, const int* __restrict__ ssrc3,
                          const float* __restrict__ el, const float* __restrict__ er,
                          const __half* __restrict__ feats, const float* __restrict__ gatB,
                          float* __restrict__ eall){
    pdl_wait();
    int gw = (blockIdx.x*blockDim.x + threadIdx.x) >> 5;
    int lane = threadIdx.x & 31;
    int u = gw >> 1;          // node index
    int half = gw & 1;        // which 128-col half (heads 0-1 or 2-3)
    if (u >= NGAT) return;
    const int* offs; const int* ssrc; int w, gi, nodeoff;
    if (u < Pn){ offs = offsg0; ssrc = ssrc0; w = u; gi = 0; nodeoff = GOFF0; }
    else if (u < 2*Pn){ offs = offsg1; ssrc = ssrc1; w = u - Pn; gi = 1; nodeoff = GOFF1; }
    else if (u < 2*Pn + Mn){ offs = offsg2; ssrc = ssrc2; w = u - 2*Pn; gi = 2; nodeoff = GOFF2; }
    else { offs = offsg3; ssrc = ssrc3; w = u - 2*Pn - Mn; gi = 3; nodeoff = GOFF3; }
    int beg = offs[w], end = offs[w+1];
    int ci = half*32 + lane;     // float2 index within row (4 half cols per lane)
    float4 erv4 = *(const float4*)(er + (size_t)u*4);
    float er_a = half ? erv4.z : erv4.x;
    float er_b = half ? erv4.w : erv4.y;

    float ma = -1e30f, mb = -1e30f;
    for (int e = beg + lane; e < end; e += 32){
        int s = ssrc[e];
        float4 elv = *(const float4*)(el + (size_t)(nodeoff + s)*4);
        float el_a = half ? elv.z : elv.x;
        float el_b = half ? elv.w : elv.y;
        ma = fmaxf(ma, lrelu2(el_a + er_a));
        mb = fmaxf(mb, lrelu2(el_b + er_b));
    }
    #pragma unroll
    for (int o = 16; o >= 1; o >>= 1){
        ma = fmaxf(ma, __shfl_xor_sync(0xffffffffu, ma, o));
        mb = fmaxf(mb, __shfl_xor_sync(0xffffffffu, mb, o));
    }

    bool hiHead = (lane >= 16);
    float sa = 0.f, sb = 0.f;
    float a0=0.f,a1=0.f,a2=0.f,a3=0.f;
    // prefetch first edge tile (ssrc + its el row; index 0 is always valid)
    int sp = 0;
    {
        int e0 = beg + lane;
        if (e0 < end) sp = ssrc[e0];
    }
    float4 elp = *(const float4*)(el + (size_t)(nodeoff + sp)*4);
    for (int base = beg; base < end; base += 32){
        int sidx = sp;
        float4 elv = elp;
        bool valid = (base + lane < end);
        // prefetch next tile
        int en = base + 32 + lane;
        if (en < end) sp = ssrc[en];
        elp = *(const float4*)(el + (size_t)(nodeoff + sp)*4);
        float ua = 0.f, ub = 0.f;
        if (valid){
            float el_a = half ? elv.z : elv.x;
            float el_b = half ? elv.w : elv.y;
            ua = __expf(lrelu2(el_a + er_a) - ma);
            ub = __expf(lrelu2(el_b + er_b) - mb);
        } else {
            sidx = 0;
        }
        sa += ua; sb += ub;
        int cnt = min(32, end - base);
        for (int k = 0; k < cnt; k++){
            int ss = __shfl_sync(0xffffffffu, sidx, k);
            float qa = __shfl_sync(0xffffffffu, ua, k);
            float qb = __shfl_sync(0xffffffffu, ub, k);
            float qq = hiHead ? qb : qa;
            float2 raw = ((const float2*)(feats + (size_t)(nodeoff + ss)*Fn))[ci];
            const __half2* hp = (const __half2*)&raw;
            float2 f0 = __half22float2(hp[0]);
            float2 f1 = __half22float2(hp[1]);
            a0 = fmaf(qq,f0.x,a0); a1 = fmaf(qq,f0.y,a1);
            a2 = fmaf(qq,f1.x,a2); a3 = fmaf(qq,f1.y,a3);
        }
    }
    #pragma unroll
    for (int o = 16; o >= 1; o >>= 1){
        sa += __shfl_xor_sync(0xffffffffu, sa, o);
        sb += __shfl_xor_sync(0xffffffffu, sb, o);
    }
    float dd = hiHead ? sb : sa;
    dd = 1.f/(dd + 1e-9f);
    a0 *= dd; a1 *= dd; a2 *= dd; a3 *= dd;

    const float* bias = gatB + gi*256;
    float4 bb = ((const float4*)bias)[ci];
    a0 += bb.x; a1 += bb.y; a2 += bb.z; a3 += bb.w;
    a0 = a0 > 0.f ? a0 : expm1f(a0);
    a1 = a1 > 0.f ? a1 : expm1f(a1);
    a2 = a2 > 0.f ? a2 : expm1f(a2);
    a3 = a3 > 0.f ? a3 : expm1f(a3);
    ((float4*)(eall + (size_t)u * Fn))[ci] = make_float4(a0,a1,a2,a3);
}

// ---------------- semantic attention scores, 16-row tiles ----------------
__global__ void k_semscore(const float* __restrict__ eall,
                           const float* __restrict__ W1, const float* __restrict__ b1,
                           const float* __restrict__ W2, float* wsum){
    pdl_wait();
    int zi = blockIdx.y;
    const float* z = eall + (size_t)((zi==0)?GOFF0:(zi==1)?GOFF1:(zi==2)?GOFF2:GOFF3)*Fn;
    int n = (zi < 2) ? Pn : Mn;
    int r0 = blockIdx.x * 16;
    if (r0 >= n) return;
    __shared__ float sZ[16][256];
    for (int i = threadIdx.x; i < 16*256; i += 128){
        int r = i >> 8, k = i & 255;
        sZ[r][k] = (r0 + r < n) ? z[(size_t)(r0+r)*256 + k] : 0.f;
    }
    __syncthreads();
    int c = threadIdx.x;
    float bc = b1[c];
    float acc[16];
    #pragma unroll
    for (int r = 0; r < 16; r++) acc[r] = bc;
    for (int k = 0; k < 256; k++){
        float w1v = W1[k*128 + c];
        #pragma unroll
        for (int r = 0; r < 16; r++)
            acc[r] = fmaf(sZ[r][k], w1v, acc[r]);
    }
    float w2 = W2[c];
    float local = 0.f;
    #pragma unroll
    for (int r = 0; r < 16; r++)
        if (r0 + r < n) local += tanh_fast(acc[r]) * w2;
    for (int o = 16; o >= 1; o >>= 1)
        local += __shfl_xor_sync(0xffffffffu, local, o);
    __shared__ float red[4];
    if ((threadIdx.x & 31) == 0) red[threadIdx.x >> 5] = local;
    __syncthreads();
    if (threadIdx.x == 0)
        atomicAdd(&wsum[zi], red[0] + red[1] + red[2] + red[3]);
}

// fused combine: patient then med; med part accumulates colsum of relu(med)
__global__ void k_combine2(const float* __restrict__ eall, const float* __restrict__ ws,
                           float* __restrict__ outPat, float* __restrict__ outMed,
                           float* __restrict__ colsum){
    pdl_wait();
    int i = blockIdx.x*blockDim.x + threadIdx.x;
    if (i < Pn*Fn){
        float w0 = ws[0]*(1.f/(float)Pn), w1 = ws[1]*(1.f/(float)Pn);
        float m = fmaxf(w0, w1);
        float x0 = __expf(w0 - m), x1 = __expf(w1 - m);
        float inv = 1.f/(x0 + x1);
        outPat[i] = (x0*inv)*eall[GOFF0*Fn + i] + (x1*inv)*eall[GOFF1*Fn + i];
    } else if (i < Pn*Fn + Mn*Fn){
        int j = i - Pn*Fn;
        float w0 = ws[2]*(1.f/(float)Mn), w1 = ws[3]*(1.f/(float)Mn);
        float m = fmaxf(w0, w1);
        float x0 = __expf(w0 - m), x1 = __expf(w1 - m);
        float inv = 1.f/(x0 + x1);
        float v = (x0*inv)*eall[GOFF2*Fn + j] + (x1*inv)*eall[GOFF3*Fn + j];
        outMed[j] = v;
        atomicAdd(&colsum[j & 255], fmaxf(v, 0.f));
    }
}

// tvec[j] = colsum . W_bot[:,j] -- warp per output, shuffle reduce
__global__ void k_medt(const float* __restrict__ colsum, const float* __restrict__ outW,
                       float* __restrict__ tvec){
    pdl_wait();
    int wpb = blockDim.x >> 5;
    int j = blockIdx.x * wpb + (threadIdx.x >> 5);
    int lane = threadIdx.x & 31;
    if (j >= Mn) return;
    float acc = 0.f;
    #pragma unroll
    for (int kk = 0; kk < 8; kk++){
        int k = kk*32 + lane;
        acc = fmaf(colsum[k], outW[(256 + k)*Mn + j], acc);
    }
    #pragma unroll
    for (int o = 16; o >= 1; o >>= 1)
        acc += __shfl_xor_sync(0xffffffffu, acc, o);
    if (lane == 0) tvec[j] = acc;
}

// simi_pm[p,j] = M*( relu(patient[p]) . W_top[:,j] + b[j] ) + t[j]  -- 8-row tiles
// Epilogue: re-zero cnt/wsum/colsum to restore the entry invariant for the next replay.
__global__ void k_final(const float* __restrict__ patient, const float* __restrict__ outW,
                        const float* __restrict__ outb, const float* __restrict__ tvec,
                        float* __restrict__ simi,
                        int* cnt, float* wsum, float* colsum){
    pdl_wait();
    __shared__ float sA[256][8];
    int r0 = blockIdx.x * 8;
    for (int i = threadIdx.x; i < 8*256; i += blockDim.x){
        int r = i >> 8, k = i & 255;
        float v = (r0 + r < Pn) ? patient[(size_t)(r0+r)*256 + k] : 0.f;
        sA[k][r] = fmaxf(v, 0.f);
    }
    __syncthreads();
    int j = threadIdx.x;
    if (j < Mn){
        float acc[8];
        #pragma unroll
        for (int r = 0; r < 8; r++) acc[r] = 0.f;
        for (int k = 0; k < 256; k++){
            float wv = outW[k*Mn + j];
            const float4 a40 = *(const float4*)&sA[k][0];
            const float4 a41 = *(const float4*)&sA[k][4];
            acc[0] = fmaf(a40.x, wv, acc[0]); acc[1] = fmaf(a40.y, wv, acc[1]);
            acc[2] = fmaf(a40.z, wv, acc[2]); acc[3] = fmaf(a40.w, wv, acc[3]);
            acc[4] = fmaf(a41.x, wv, acc[4]); acc[5] = fmaf(a41.y, wv, acc[5]);
            acc[6] = fmaf(a41.z, wv, acc[6]); acc[7] = fmaf(a41.w, wv, acc[7]);
        }
        float tv = tvec[j], bb = outb[j];
        #pragma unroll
        for (int r = 0; r < 8; r++)
            if (r0 + r < Pn)
                simi[(size_t)(r0+r)*Mn + j] = (float)Mn * (acc[r] + bb) + tv;
    }
    // epilogue: restore zero invariant (grid covers 250*160 = 40000 >= CNT_TOT)
    int g = blockIdx.x * blockDim.x + threadIdx.x;
    if (g < CNT_TOT) cnt[g] = 0;
    if (g < 4) wsum[g] = 0.f;
    if (g < Fn) colsum[g] = 0.f;
}

// ---------------- host launch ----------------
template <typename T>
static T* symaddr(const void* sym){
    void* p = nullptr;
    cudaGetSymbolAddress(&p, sym);
    return (T*)p;
}

// PDL launch helper: dependent kernel may be dispatched while predecessor drains.
template <typename F, typename... Args>
static void pdl_launch(F f, dim3 grid, dim3 block, Args... args){
    cudaLaunchConfig_t cfg = {};
    cfg.gridDim = grid;
    cfg.blockDim = block;
    cudaLaunchAttribute attr[1];
    attr[0].id = cudaLaunchAttributeProgrammaticStreamSerialization;
    attr[0].val.programmaticStreamSerializationAllowed = 1;
    cfg.attrs = attr;
    cfg.numAttrs = 1;
    cudaLaunchKernelEx(&cfg, f, args...);
}

extern "C" void kernel_launch(void* const* d_in, const int* in_sizes, int n_in,
                              void* d_out, int out_size){
    const int*   a1r = (const int*)  d_in[0];
    const int*   a1c = (const int*)  d_in[1];
    const float* a1v = (const float*)d_in[2];
    const int*   a2r = (const int*)  d_in[3];
    const int*   a2c = (const int*)  d_in[4];
    const float* a2v = (const float*)d_in[5];
    const int*   g0s = (const int*)  d_in[6];
    const int*   g0d = (const int*)  d_in[7];
    const int*   g1s = (const int*)  d_in[8];
    const int*   g1d = (const int*)  d_in[9];
    const int*   g2s = (const int*)  d_in[10];
    const int*   g2d = (const int*)  d_in[11];
    const int*   g3s = (const int*)  d_in[12];
    const int*   g3d = (const int*)  d_in[13];
    int kr = (n_in >= 27) ? 1 : 0;
    const float* pE    = (const float*)d_in[14 + kr];
    const float* mE    = (const float*)d_in[15 + kr];
    const float* dE    = (const float*)d_in[16 + kr];
    const float* gatW  = (const float*)d_in[17 + kr];
    const float* gatAl = (const float*)d_in[18 + kr];
    const float* gatAr = (const float*)d_in[19 + kr];
    const float* gatB  = (const float*)d_in[20 + kr];
    const float* saW1  = (const float*)d_in[21 + kr];
    const float* saB1  = (const float*)d_in[22 + kr];
    const float* saW2  = (const float*)d_in[23 + kr];
    const float* outW  = (const float*)d_in[24 + kr];
    const float* outB  = (const float*)d_in[25 + kr];
    float* out = (float*)d_out;

    __half* hlat1a = symaddr<__half>(g_hlat1a); __half* hlat1b = symaddr<__half>(g_hlat1b);
    __half* hlat2a = symaddr<__half>(g_hlat2a); __half* hlat2b = symaddr<__half>(g_hlat2b);
    float* acc1  = symaddr<float>(g_acc1);
    float* acc2  = symaddr<float>(g_acc2);
    int* cnt   = symaddr<int>(g_cnt);
    int* offs1 = symaddr<int>(g_offs1); int* cur1 = symaddr<int>(g_cur1);
    int* offs2 = symaddr<int>(g_offs2); int* cur2 = symaddr<int>(g_cur2);
    int2* epack1 = symaddr<int2>(g_epack1);
    int2* epack2 = symaddr<int2>(g_epack2);
    int* offsg0 = symaddr<int>(g_offsg0); int* curg0 = symaddr<int>(g_curg0); int* ssrc0 = symaddr<int>(g_ssrc0);
    int* offsg1 = symaddr<int>(g_offsg1); int* curg1 = symaddr<int>(g_curg1); int* ssrc1 = symaddr<int>(g_ssrc1);
    int* offsg2 = symaddr<int>(g_offsg2); int* curg2 = symaddr<int>(g_curg2); int* ssrc2 = symaddr<int>(g_ssrc2);
    int* offsg3 = symaddr<int>(g_offsg3); int* curg3 = symaddr<int>(g_curg3); int* ssrc3 = symaddr<int>(g_ssrc3);
    __half* feats = symaddr<__half>(g_feats);
    __half* hgatW = symaddr<__half>(g_hgatW);
    float* el = symaddr<float>(g_el); float* er = symaddr<float>(g_er);
    float* eall = symaddr<float>(g_eall);
    float* wsum = symaddr<float>(g_wsum);
    float* colsum = symaddr<float>(g_colsum);
    float* tvec = symaddr<float>(g_tvec);

    const int B = 256;

    // ---- fused init+hist+W-convert (cnt is zero by invariant) ----
    k_init_hist<<<((N1n+N2n)*Fn/2+B-1)/B, B>>>(pE, mE, dE, gatW, hlat1a, hlat2a, hgatW,
                                               a1r, a2r, g0d, g1d, g2d, g3d, cnt);
    pdl_launch(k_exscan_all, dim3(6), dim3(1024),
               (const int*)cnt, offs1, cur1, offs2, cur2,
               offsg0, curg0, offsg1, curg1, offsg2, curg2, offsg3, curg3);
    pdl_launch(k_scatter_all, dim3((EHTOT+B-1)/B), dim3(B),
               a1r, a1c, a1v, a2r, a2c, a2v,
               g0d, g0s, g1d, g1s, g2d, g2s, g3d, g3s,
               cur1, epack1, cur2, epack2,
               curg0, ssrc0, curg1, ssrc1, curg2, ssrc2, curg3, ssrc3);

    // ---- 2 GNN layers, 2 warps per row ----
    int spmmBlocks = (2*(N1n + N2n) + 7)/8;
    pdl_launch(k_spmm2, dim3(spmmBlocks), dim3(B),
               (const int*)offs1, (const int2*)epack1, (const __half*)hlat1a, hlat1b, acc1,
               (const int*)offs2, (const int2*)epack2, (const __half*)hlat2a, hlat2b, acc2,
               0, (float*)nullptr, (float*)nullptr);
    pdl_launch(k_spmm2, dim3(spmmBlocks), dim3(B),
               (const int*)offs1, (const int2*)epack1, (const __half*)hlat1b, hlat1a, acc1,
               (const int*)offs2, (const int2*)epack2, (const __half*)hlat2b, hlat2a, acc2,
               1, out + OUT_MGCN, out + OUT_DGCN);

    // ---- batched GEMM (half W) + fused el/er (16-row tiles) ----
    pdl_launch(k_gemm_elr, dim3((Pn+15)/16, 4), dim3(256),
               (const float*)acc1, (const float*)acc2, (const __half*)hgatW, gatAl, gatAr,
               feats, el, er);

    // ---- batched GAT aggregate (2 warps per node, prefetch) ----
    pdl_launch(k_gat_all, dim3((2*NGAT+7)/8), dim3(B),
               (const int*)offsg0, (const int*)ssrc0, (const int*)offsg1, (const int*)ssrc1,
               (const int*)offsg2, (const int*)ssrc2, (const int*)offsg3, (const int*)ssrc3,
               (const float*)el, (const float*)er, (const __half*)feats, gatB, eall);

    // ---- semantic attention (16-row tiles) ----
    pdl_launch(k_semscore, dim3((Pn+15)/16, 4), dim3(128),
               (const float*)eall, saW1, saB1, saW2, wsum);
    pdl_launch(k_combine2, dim3(((Pn+Mn)*Fn+B-1)/B), dim3(B),
               (const float*)eall, (const float*)wsum, out + OUT_PAT, out + OUT_MED, colsum);

    // ---- final similarity ----
    pdl_launch(k_medt, dim3((Mn*32+B-1)/B), dim3(B),
               (const float*)colsum, outW, tvec);
    pdl_launch(k_final, dim3((Pn+7)/8), dim3(160),
               (const float*)(out + OUT_PAT), outW, outB, (const float*)tvec,
               out + OUT_SIMI, cnt, wsum, colsum);
}